// round 4
// baseline (speedup 1.0000x reference)
#include <cuda_runtime.h>

// cost_volumn: out[n,y,x, i*9+j] = (1/128) * sum_c f1[n,y,x,c] * f2[n, y+i-4, x+j-4, c]
// f1,f2: [8,128,256,128] f32 NHWC; out: [8,128,256,81] f32. Zero padding outside.

#define DN 8
#define DH 128
#define DW 256
#define DC 128
#define RAD 4
#define NDX 9
#define NOFF 81

constexpr int CC      = 8;            // channels per smem chunk
constexpr int NCH     = DC / CC;      // 16 chunks
constexpr int PX      = 8;            // pixels per thread
constexpr int NG      = DW / PX;      // 32 x-groups
constexpr int THREADS = NG * NDX;     // 288 (9 warps, warp = dy)
constexpr int XCOLS   = DW + 2 * RAD; // 264 logical f2 columns (x+4)
constexpr int ROWLEN  = 276;          // padded row stride in floats (16B-aligned, bank-staggered)
constexpr int SROWS   = NDX * CC + CC;// 9*8 f2 rows + 8 f1 rows = 80
constexpr int SMEM_BYTES = SROWS * ROWLEN * 4;  // 88,320 B

// XOR swizzle on 16B chunks: kills the 8-way conflict of 32B-strided lane windows.
__device__ __forceinline__ int swzidx(int xc) {
    int j = xc >> 2;
    j ^= (j >> 3) & 7;
    return (j << 2) | (xc & 3);
}
__device__ __forceinline__ int swzchunk4(int j) {  // float offset of logical chunk j
    return (j ^ ((j >> 3) & 7)) << 2;
}

extern __shared__ float smem[];

__global__ __launch_bounds__(THREADS, 2)
void costvol_kernel(const float* __restrict__ f1,
                    const float* __restrict__ f2,
                    float* __restrict__ out)
{
    const int y0  = blockIdx.x;   // y row
    const int n   = blockIdx.y;   // batch
    const int tid = threadIdx.x;
    const int i   = tid >> 5;     // dy index 0..8 (warp id)
    const int g   = tid & 31;     // x-group: pixels 8g..8g+7

    float* sF2 = smem;                          // [9][CC][ROWLEN], transposed + swizzled
    float* sF1 = smem + NDX * CC * ROWLEN;      // [CC][ROWLEN]

    // Physical float offsets of this lane's chunks (fixed for the whole kernel).
    const int pw0 = swzchunk4(2 * g + 0);
    const int pw1 = swzchunk4(2 * g + 1);
    const int pw2 = swzchunk4(2 * g + 2);
    const int pw3 = swzchunk4(2 * g + 3);

    float acc[NDX][PX];
    #pragma unroll
    for (int a = 0; a < NDX; ++a)
        #pragma unroll
        for (int b = 0; b < PX; ++b) acc[a][b] = 0.f;

    const int rowPix = (n * DH + y0) * DW;  // pixel-index base of this row

    for (int cc = 0; cc < NCH; ++cc) {
        __syncthreads();
        // ---------------- stage chunk cc into smem (transposed + swizzled) ----------
        const int cofs = cc * CC;
        const int TOTV = (NDX * XCOLS + DW) * 2;  // float4 units
        for (int t = tid; t < TOTV; t += THREADS) {
            if (t < NDX * XCOLS * 2) {
                const int half = t & 1;
                const int u    = t >> 1;
                const int xcol = u % XCOLS;
                const int row  = u / XCOLS;
                const int y2 = y0 + row - RAD;
                const int x2 = xcol - RAD;
                float4 v = make_float4(0.f, 0.f, 0.f, 0.f);
                if ((unsigned)y2 < DH && (unsigned)x2 < DW) {
                    v = *reinterpret_cast<const float4*>(
                        f2 + (size_t)((n * DH + y2) * DW + x2) * DC + cofs + half * 4);
                }
                float* dst = sF2 + (row * CC + half * 4) * ROWLEN + swzidx(xcol);
                dst[0]          = v.x;
                dst[ROWLEN]     = v.y;
                dst[2 * ROWLEN] = v.z;
                dst[3 * ROWLEN] = v.w;
            } else {
                const int u    = t - NDX * XCOLS * 2;
                const int half = u & 1;
                const int x    = u >> 1;
                float4 v = *reinterpret_cast<const float4*>(
                    f1 + (size_t)(rowPix + x) * DC + cofs + half * 4);
                float* dst = sF1 + (half * 4) * ROWLEN + swzidx(x);
                dst[0]          = v.x;
                dst[ROWLEN]     = v.y;
                dst[2 * ROWLEN] = v.z;
                dst[3 * ROWLEN] = v.w;
            }
        }
        __syncthreads();
        // ---------------- compute: 8 channels x 72 FMAs, all register-resident -------
        #pragma unroll
        for (int c = 0; c < CC; ++c) {
            const float* r1 = sF1 + c * ROWLEN;
            const float4 a0 = *reinterpret_cast<const float4*>(r1 + pw0);
            const float4 a1 = *reinterpret_cast<const float4*>(r1 + pw1);
            const float* r2 = sF2 + (i * CC + c) * ROWLEN;
            const float4 w0 = *reinterpret_cast<const float4*>(r2 + pw0);
            const float4 w1 = *reinterpret_cast<const float4*>(r2 + pw1);
            const float4 w2 = *reinterpret_cast<const float4*>(r2 + pw2);
            const float4 w3 = *reinterpret_cast<const float4*>(r2 + pw3);
            const float a[PX]  = {a0.x, a0.y, a0.z, a0.w, a1.x, a1.y, a1.z, a1.w};
            const float w[16]  = {w0.x, w0.y, w0.z, w0.w, w1.x, w1.y, w1.z, w1.w,
                                  w2.x, w2.y, w2.z, w2.w, w3.x, w3.y, w3.z, w3.w};
            #pragma unroll
            for (int dx = 0; dx < NDX; ++dx)
                #pragma unroll
                for (int p = 0; p < PX; ++p)
                    acc[dx][p] = fmaf(a[p], w[p + dx], acc[dx][p]);
        }
    }

    // ---------------- epilogue: block writes one contiguous 83KB region -------------
    const float inv = 1.0f / (float)DC;
    #pragma unroll
    for (int p = 0; p < PX; ++p) {
        const int ob = (rowPix + g * PX + p) * NOFF + i * NDX;
        #pragma unroll
        for (int dx = 0; dx < NDX; ++dx)
            out[ob + dx] = acc[dx][p] * inv;
    }
}

extern "C" void kernel_launch(void* const* d_in, const int* in_sizes, int n_in,
                              void* d_out, int out_size)
{
    const float* f1 = (const float*)d_in[0];
    const float* f2 = (const float*)d_in[1];
    float* out      = (float*)d_out;

    cudaFuncSetAttribute(costvol_kernel,
                         cudaFuncAttributeMaxDynamicSharedMemorySize, SMEM_BYTES);
    dim3 grid(DH, DN);  // y fastest -> adjacent blocks share f2 halo rows in L2
    costvol_kernel<<<grid, THREADS, SMEM_BYTES>>>(f1, f2, out);
}

// round 5
// speedup vs baseline: 1.2554x; 1.2554x over previous
#include <cuda_runtime.h>

// cost_volumn: out[n,y,x, i*9+j] = (1/128) * sum_c f1[n,y,x,c] * f2[n, y+i-4, x+j-4, c]
// f1,f2: [8,128,256,128] f32 NHWC; out: [8,128,256,81] f32. Zero padding outside.

#define DN 8
#define DH 128
#define DW 256
#define DC 128
#define RAD 4
#define NDX 9
#define NOFF 81

constexpr int YB      = 2;             // output rows per block
constexpr int CC      = 16;            // channels per smem chunk
constexpr int NCH     = DC / CC;       // 8 chunks
constexpr int PX      = 8;             // pixels per thread
constexpr int THREADS = 576;           // 18 warps = YB * NDX; warp=(row,dy), lane=x-group
constexpr int XCOLS   = DW + 2 * RAD;  // 264 logical f2 columns
constexpr int YROWS   = YB + 2 * RAD;  // 10 f2 rows staged per block
constexpr int ROWLEN  = 276;           // padded row stride (floats)
constexpr int F2ROWS  = YROWS * CC;    // 160
constexpr int F1ROWS  = YB * CC;       // 32
constexpr int SMEM_BYTES = (F2ROWS + F1ROWS) * ROWLEN * 4;  // 211,968 B

constexpr int F2ITEMS = YROWS * XCOLS * 4;       // 10560 float4 staging items
constexpr int TOTITEMS = F2ITEMS + YB * DW * 4;  // 12608

// XOR swizzle on 16B chunks: distributes the 32B-strided lane windows across banks.
__device__ __forceinline__ int swzidx(int xc) {
    int j = xc >> 2;
    j ^= (j >> 3) & 7;
    return (j << 2) | (xc & 3);
}
__device__ __forceinline__ int swzchunk4(int j) {  // float offset of logical 16B chunk j
    return (j ^ ((j >> 3) & 7)) << 2;
}

extern __shared__ float smem[];

__global__ __launch_bounds__(THREADS, 1)
void costvol_kernel(const float* __restrict__ f1,
                    const float* __restrict__ f2,
                    float* __restrict__ out)
{
    const int y0  = blockIdx.x * YB;   // first output row of this block
    const int n   = blockIdx.y;        // batch
    const int tid = threadIdx.x;
    const int w   = tid >> 5;          // warp 0..17
    const int r   = w / NDX;           // output row within block (0..1)
    const int i   = w % NDX;           // dy index 0..8
    const int g   = tid & 31;          // x-group: pixels 8g..8g+7

    float* sF2 = smem;                           // [YROWS*CC][ROWLEN] transposed+swizzled
    float* sF1 = smem + F2ROWS * ROWLEN;         // [YB*CC][ROWLEN]

    // Physical float offsets of this lane's 16B chunks (fixed for the whole kernel).
    const int pw0 = swzchunk4(2 * g + 0);
    const int pw1 = swzchunk4(2 * g + 1);
    const int pw2 = swzchunk4(2 * g + 2);
    const int pw3 = swzchunk4(2 * g + 3);

    float acc[NDX][PX];
    #pragma unroll
    for (int a = 0; a < NDX; ++a)
        #pragma unroll
        for (int b = 0; b < PX; ++b) acc[a][b] = 0.f;

    const int rowPix = (n * DH + y0) * DW;  // pixel index of (n, y0, 0)

    for (int cc = 0; cc < NCH; ++cc) {
        __syncthreads();
        // ------------ stage chunk cc (CC=16 channels) into smem, transposed ---------
        const int cofs = cc * CC;
        for (int t = tid; t < TOTITEMS; t += THREADS) {
            if (t < F2ITEMS) {
                const int q    = t & 3;        // channel quad 0..3
                const unsigned u = (unsigned)t >> 2;
                const int xcol = (int)(u % (unsigned)XCOLS);
                const int row  = (int)(u / (unsigned)XCOLS);
                const int y2 = y0 + row - RAD;
                const int x2 = xcol - RAD;
                float4 v = make_float4(0.f, 0.f, 0.f, 0.f);
                if ((unsigned)y2 < DH && (unsigned)x2 < DW) {
                    v = *reinterpret_cast<const float4*>(
                        f2 + (size_t)((n * DH + y2) * DW + x2) * DC + cofs + q * 4);
                }
                float* dst = sF2 + (row * CC + q * 4) * ROWLEN + swzidx(xcol);
                dst[0]          = v.x;
                dst[ROWLEN]     = v.y;
                dst[2 * ROWLEN] = v.z;
                dst[3 * ROWLEN] = v.w;
            } else {
                const int t2   = t - F2ITEMS;
                const int q    = t2 & 3;
                const int u    = t2 >> 2;      // 0..511
                const int x    = u & (DW - 1);
                const int r2   = u >> 8;       // 0..1
                float4 v = *reinterpret_cast<const float4*>(
                    f1 + (size_t)(rowPix + r2 * DW + x) * DC + cofs + q * 4);
                float* dst = sF1 + (r2 * CC + q * 4) * ROWLEN + swzidx(x);
                dst[0]          = v.x;
                dst[ROWLEN]     = v.y;
                dst[2 * ROWLEN] = v.z;
                dst[3 * ROWLEN] = v.w;
            }
        }
        __syncthreads();
        // ------------ compute: 16 channels x 72 FMAs, register-resident window ------
        #pragma unroll
        for (int c = 0; c < CC; ++c) {
            const float* r1 = sF1 + (r * CC + c) * ROWLEN;
            const float4 a0 = *reinterpret_cast<const float4*>(r1 + pw0);
            const float4 a1 = *reinterpret_cast<const float4*>(r1 + pw1);
            const float* r2 = sF2 + ((r + i) * CC + c) * ROWLEN;
            const float4 w0 = *reinterpret_cast<const float4*>(r2 + pw0);
            const float4 w1 = *reinterpret_cast<const float4*>(r2 + pw1);
            const float4 w2 = *reinterpret_cast<const float4*>(r2 + pw2);
            const float4 w3 = *reinterpret_cast<const float4*>(r2 + pw3);
            const float a[PX] = {a0.x, a0.y, a0.z, a0.w, a1.x, a1.y, a1.z, a1.w};
            const float wv[16] = {w0.x, w0.y, w0.z, w0.w, w1.x, w1.y, w1.z, w1.w,
                                  w2.x, w2.y, w2.z, w2.w, w3.x, w3.y, w3.z, w3.w};
            #pragma unroll
            for (int dx = 0; dx < NDX; ++dx)
                #pragma unroll
                for (int p = 0; p < PX; ++p)
                    acc[dx][p] = fmaf(a[p], wv[p + dx], acc[dx][p]);
        }
    }

    // ------------ epilogue ------------------------------------------------------
    const float inv = 1.0f / (float)DC;
    const int pixBase = rowPix + r * DW + g * PX;
    #pragma unroll
    for (int p = 0; p < PX; ++p) {
        const int ob = (pixBase + p) * NOFF + i * NDX;
        #pragma unroll
        for (int dx = 0; dx < NDX; ++dx)
            out[ob + dx] = acc[dx][p] * inv;
    }
}

extern "C" void kernel_launch(void* const* d_in, const int* in_sizes, int n_in,
                              void* d_out, int out_size)
{
    const float* f1 = (const float*)d_in[0];
    const float* f2 = (const float*)d_in[1];
    float* out      = (float*)d_out;

    cudaFuncSetAttribute(costvol_kernel,
                         cudaFuncAttributeMaxDynamicSharedMemorySize, SMEM_BYTES);
    dim3 grid(DH / YB, DN);  // y fastest -> adjacent blocks share f2 halo rows in L2
    costvol_kernel<<<grid, THREADS, SMEM_BYTES>>>(f1, f2, out);
}